// round 15
// baseline (speedup 1.0000x reference)
#include <cuda_runtime.h>
#include <cuda_fp16.h>
#include <cstdint>

// ---------------- problem constants ----------------
#define MAXN 100000
#define MAXE 3200000
#define NG   64

__device__ __forceinline__ uint32_t smem_to_u32(const void* p) {
    uint32_t a;
    asm("{ .reg .u64 t; cvta.to.shared.u64 t, %1; cvt.u32.u64 %0, t; }" : "=r"(a) : "l"(p));
    return a;
}
#define LDSM4(r0, r1, r2, r3, addr) \
    asm volatile("ldmatrix.sync.aligned.m8n8.x4.shared.b16 {%0,%1,%2,%3}, [%4];" \
        : "=r"(r0), "=r"(r1), "=r"(r2), "=r"(r3) : "r"(addr))
#define MMA_F16(d, a, b) \
    asm volatile("mma.sync.aligned.m16n8k16.row.col.f32.f16.f16.f32 " \
        "{%0,%1,%2,%3}, {%4,%5,%6,%7}, {%8,%9}, {%0,%1,%2,%3};" \
        : "+f"((d)[0]), "+f"((d)[1]), "+f"((d)[2]), "+f"((d)[3]) \
        : "r"((a)[0]), "r"((a)[1]), "r"((a)[2]), "r"((a)[3]), "r"((b)[0]), "r"((b)[1]))

// ---------------- device scratch (referenced ONLY from device code) ----------------
__device__ int   g_deg[MAXN];
__device__ float g_dinv[MAXN];
__device__ int   g_colptr[MAXN + 1];
__device__ int   g_cursor[MAXN];
__device__ int   g_blocksum[128];
__device__ int   g_bloff[128];
__device__ int2  g_edge[MAXE];
__device__ __align__(16) __half g_xh[(size_t)MAXN * 128];    // x in fp16
__device__ __align__(16) __half g_h1h[(size_t)MAXN * 256];   // h1 in fp16
__device__ __align__(16) __half g_b1hi[256 * 128];
__device__ __align__(16) __half g_b1lo[256 * 128];
__device__ __align__(16) __half g_b2hi[256 * 256];
__device__ __align__(16) __half g_b2lo[256 * 256];
__device__ float g_sums[NG * 256];
__device__ float g_cnt[NG];

// ---------------- prep kernels ----------------
__global__ void init_kernel(int n) {
    int i = blockIdx.x * blockDim.x + threadIdx.x;
    if (i < n) g_deg[i] = 0;
    if (i < NG * 256) g_sums[i] = 0.f;
    if (i < NG) g_cnt[i] = 0.f;
}

// fused: degree atomics + graph counts + x->fp16 + weight transpose/split
__global__ void prep_all(const int* __restrict__ ei, const int* __restrict__ batch,
                         const float4* __restrict__ X,
                         const float* __restrict__ W1, const float* __restrict__ W2,
                         int E, int n) {
    int e = blockIdx.x * blockDim.x + threadIdx.x;
    if (e < E) {
        unsigned c = (unsigned)ei[E + e];
        if (c < (unsigned)n) atomicAdd(&g_deg[c], 1);
    }
    if (e < n) atomicAdd(&g_cnt[batch[e] & (NG - 1)], 1.0f);
    if (e < n * 32) {
        float4 v = X[e];
        union { __half2 h[2]; uint2 u; } o;
        o.h[0] = __floats2half2_rn(v.x, v.y);
        o.h[1] = __floats2half2_rn(v.z, v.w);
        *(uint2*)(g_xh + (size_t)e * 4) = o.u;
    }
    if (e < 256 * 128) {
        int k = e & 127, nn = e >> 7;
        float w = W1[k * 256 + nn];
        __half h = __float2half_rn(w);
        g_b1hi[e] = h;
        g_b1lo[e] = __float2half_rn(w - __half2float(h));
    } else if (e < 256 * 128 + 256 * 256) {
        int j = e - 256 * 128;
        int k = j & 255, nn = j >> 8;
        float w = W2[k * 256 + nn];
        __half h = __float2half_rn(w);
        g_b2hi[j] = h;
        g_b2lo[j] = __float2half_rn(w - __half2float(h));
    }
}

// 3-phase multiblock scan (scan1 also computes dinv)
__global__ void scan1(int n) {
    __shared__ int wsum[32];
    int i = blockIdx.x * 1024 + threadIdx.x;
    int lane = threadIdx.x & 31, wid = threadIdx.x >> 5;
    int v = (i < n) ? g_deg[i] : 0;
    if (i < n) g_dinv[i] = rsqrtf((float)(v + 1));   // +1 self loop
    int s = v;
    #pragma unroll
    for (int off = 1; off < 32; off <<= 1) {
        int t = __shfl_up_sync(0xffffffffu, s, off);
        if (lane >= off) s += t;
    }
    if (lane == 31) wsum[wid] = s;
    __syncthreads();
    if (wid == 0) {
        int t = wsum[lane];
        int ss = t;
        #pragma unroll
        for (int off = 1; off < 32; off <<= 1) {
            int u = __shfl_up_sync(0xffffffffu, ss, off);
            if (lane >= off) ss += u;
        }
        wsum[lane] = ss - t;
    }
    __syncthreads();
    if (i < n) g_colptr[i] = wsum[wid] + s - v;
    if (threadIdx.x == 1023) g_blocksum[blockIdx.x] = wsum[31] + s;
}

__global__ void scan2(int nb, int n) {
    __shared__ int ws[4];
    int lane = threadIdx.x & 31, wid = threadIdx.x >> 5;
    int v = (threadIdx.x < nb) ? g_blocksum[threadIdx.x] : 0;
    int s = v;
    #pragma unroll
    for (int off = 1; off < 32; off <<= 1) {
        int t = __shfl_up_sync(0xffffffffu, s, off);
        if (lane >= off) s += t;
    }
    if (lane == 31) ws[wid] = s;
    __syncthreads();
    int base = 0;
    for (int w = 0; w < wid; w++) base += ws[w];
    int excl = base + s - v;
    if (threadIdx.x < nb) g_bloff[threadIdx.x] = excl;
    if (threadIdx.x == nb - 1) g_colptr[n] = excl + v;
}

__global__ void scan3(int n) {
    int i = blockIdx.x * blockDim.x + threadIdx.x;
    if (i < n) {
        int v = g_colptr[i] + g_bloff[i >> 10];
        g_colptr[i] = v;
        g_cursor[i] = v;
    }
}

__global__ void fill_kernel(const int* __restrict__ ei, int E, int n) {
    int e = blockIdx.x * blockDim.x + threadIdx.x;
    if (e >= E) return;
    unsigned r = (unsigned)ei[e];
    unsigned c = (unsigned)ei[E + e];
    if (r >= (unsigned)n || c >= (unsigned)n) return;
    int p = atomicAdd(&g_cursor[c], 1);
    g_edge[p] = make_int2((int)r, __float_as_int(g_dinv[r] * g_dinv[c]));
}

// ---------------- gather helpers ----------------
__device__ __forceinline__ void fma_h4(float4& acc, uint2 u, float w) {
    union { __half2 h[2]; uint2 u2; } cv;
    cv.u2 = u;
    float2 f0 = __half22float2(cv.h[0]), f1 = __half22float2(cv.h[1]);
    acc.x = fmaf(f0.x, w, acc.x);
    acc.y = fmaf(f0.y, w, acc.y);
    acc.z = fmaf(f1.x, w, acc.z);
    acc.w = fmaf(f1.y, w, acc.w);
}
__device__ __forceinline__ void fma_h8(float* a, uint4 u, float w) {
    union { __half2 h[4]; uint4 u4; } cv;
    cv.u4 = u;
    float2 f0 = __half22float2(cv.h[0]), f1 = __half22float2(cv.h[1]);
    float2 f2 = __half22float2(cv.h[2]), f3 = __half22float2(cv.h[3]);
    a[0] = fmaf(f0.x, w, a[0]); a[1] = fmaf(f0.y, w, a[1]);
    a[2] = fmaf(f1.x, w, a[2]); a[3] = fmaf(f1.y, w, a[3]);
    a[4] = fmaf(f2.x, w, a[4]); a[5] = fmaf(f2.y, w, a[5]);
    a[6] = fmaf(f3.x, w, a[6]); a[7] = fmaf(f3.y, w, a[7]);
}

// ---------------- fused aggregate + HMMA GEMM + bias + relu (+pool for layer 2) ----
// Each CTA: 128 output rows x all 256 cols.
// Phase 1: CSR gather of fp16 neighbor rows -> fp32 accumulate -> fp16 smem A tile.
// Phase 2: HMMA mainloop, A resident in smem, W hi/lo staged per 32-k chunk.
// Layer 1 writes h1 fp16; layer 2 fuses mean-pool via warp-reduced global atomics.
template<int LAYER>
__global__ __launch_bounds__(256, 1) void fused_layer(const float* __restrict__ bias,
                                                      const int* __restrict__ batch, int M) {
    constexpr int K = (LAYER == 1) ? 128 : 256;
    constexpr int NCH = K / 32;
    constexpr int STRIDE_A = K * 2 + 16;             // 272 / 528 (16B-aligned, conflict-free)
    constexpr uint32_t SH_OFF = (uint32_t)(128 * STRIDE_A);
    constexpr uint32_t SL_OFF = SH_OFF + 20480;
    const __half* WH = (LAYER == 1) ? g_b1hi : g_b2hi;
    const __half* WL = (LAYER == 1) ? g_b1lo : g_b2lo;

    extern __shared__ __align__(16) char smem[];
    uint32_t sb = smem_to_u32(smem);

    int tid = threadIdx.x, lane = tid & 31, wid = tid >> 5;
    int row0 = blockIdx.x * 128;

    // ---- prefetch W chunk 0 into registers (overlaps gather) ----
    uint4 pH[4], pL[4];
    auto prefetch = [&](int ch) {
        #pragma unroll
        for (int g = 0; g < 4; g++) {
            int idx = tid + g * 256;           // 0..1023
            int r = idx >> 2, c = idx & 3;     // r: W row (out col), c: 8-half group
            int gk = ch * 32 + c * 8;
            pH[g] = *(const uint4*)(WH + (size_t)r * K + gk);
            pL[g] = *(const uint4*)(WL + (size_t)r * K + gk);
        }
    };
    auto stage = [&]() {
        #pragma unroll
        for (int g = 0; g < 4; g++) {
            int idx = tid + g * 256;
            int r = idx >> 2, c = idx & 3;
            uint32_t o = (uint32_t)(r * 80 + c * 16);
            *(uint4*)(smem + SH_OFF + o) = pH[g];
            *(uint4*)(smem + SL_OFF + o) = pL[g];
        }
    };
    prefetch(0);

    // ---- phase 1: gather 128 node rows into smem A tile ----
    #pragma unroll 1
    for (int i = 0; i < 16; i++) {
        int lrow = i * 8 + wid;
        int node = row0 + lrow;
        char* arow = smem + (size_t)lrow * STRIDE_A;
        if constexpr (LAYER == 1) {
            if (node >= M) {
                *(uint2*)(arow + lane * 8) = make_uint2(0, 0);
                continue;
            }
            const uint2* Xh = (const uint2*)g_xh;
            float di = g_dinv[node];
            float self = di * di;
            union { __half2 h[2]; uint2 u; } cv;
            cv.u = Xh[(size_t)node * 32 + lane];
            float2 f0 = __half22float2(cv.h[0]), f1 = __half22float2(cv.h[1]);
            float4 acc = make_float4(f0.x * self, f0.y * self, f1.x * self, f1.y * self);
            int s = g_colptr[node], e = g_colptr[node + 1];
            int p = s;
            for (; p + 4 <= e; p += 4) {
                int2 e0 = g_edge[p], e1 = g_edge[p + 1], e2 = g_edge[p + 2], e3 = g_edge[p + 3];
                uint2 u0 = Xh[(size_t)e0.x * 32 + lane];
                uint2 u1 = Xh[(size_t)e1.x * 32 + lane];
                uint2 u2 = Xh[(size_t)e2.x * 32 + lane];
                uint2 u3 = Xh[(size_t)e3.x * 32 + lane];
                fma_h4(acc, u0, __int_as_float(e0.y));
                fma_h4(acc, u1, __int_as_float(e1.y));
                fma_h4(acc, u2, __int_as_float(e2.y));
                fma_h4(acc, u3, __int_as_float(e3.y));
            }
            for (; p < e; p++) {
                int2 ed = g_edge[p];
                fma_h4(acc, Xh[(size_t)ed.x * 32 + lane], __int_as_float(ed.y));
            }
            union { __half2 h[2]; uint2 u; } o;
            o.h[0] = __floats2half2_rn(acc.x, acc.y);
            o.h[1] = __floats2half2_rn(acc.z, acc.w);
            *(uint2*)(arow + lane * 8) = o.u;
        } else {
            if (node >= M) {
                *(uint4*)(arow + lane * 16) = make_uint4(0, 0, 0, 0);
                continue;
            }
            const uint4* Xh = (const uint4*)g_h1h;
            float di = g_dinv[node];
            float self = di * di;
            union { __half2 h[4]; uint4 u; } cv;
            cv.u = Xh[(size_t)node * 32 + lane];
            float a[8];
            {
                float2 f0 = __half22float2(cv.h[0]), f1 = __half22float2(cv.h[1]);
                float2 f2 = __half22float2(cv.h[2]), f3 = __half22float2(cv.h[3]);
                a[0] = f0.x * self; a[1] = f0.y * self;
                a[2] = f1.x * self; a[3] = f1.y * self;
                a[4] = f2.x * self; a[5] = f2.y * self;
                a[6] = f3.x * self; a[7] = f3.y * self;
            }
            int s = g_colptr[node], e = g_colptr[node + 1];
            int p = s;
            for (; p + 4 <= e; p += 4) {
                int2 e0 = g_edge[p], e1 = g_edge[p + 1], e2 = g_edge[p + 2], e3 = g_edge[p + 3];
                uint4 u0 = Xh[(size_t)e0.x * 32 + lane];
                uint4 u1 = Xh[(size_t)e1.x * 32 + lane];
                uint4 u2 = Xh[(size_t)e2.x * 32 + lane];
                uint4 u3 = Xh[(size_t)e3.x * 32 + lane];
                fma_h8(a, u0, __int_as_float(e0.y));
                fma_h8(a, u1, __int_as_float(e1.y));
                fma_h8(a, u2, __int_as_float(e2.y));
                fma_h8(a, u3, __int_as_float(e3.y));
            }
            for (; p < e; p++) {
                int2 ed = g_edge[p];
                fma_h8(a, Xh[(size_t)ed.x * 32 + lane], __int_as_float(ed.y));
            }
            union { __half2 h[4]; uint4 u; } o;
            o.h[0] = __floats2half2_rn(a[0], a[1]);
            o.h[1] = __floats2half2_rn(a[2], a[3]);
            o.h[2] = __floats2half2_rn(a[4], a[5]);
            o.h[3] = __floats2half2_rn(a[6], a[7]);
            *(uint4*)(arow + lane * 16) = o.u;
        }
    }
    stage();
    __syncthreads();

    // ---- phase 2: HMMA mainloop; warps 4M x 2N, warp tile 32x128 ----
    int wm = wid & 3, wn = wid >> 2;
    float acc[2][16][4];
    #pragma unroll
    for (int i = 0; i < 2; i++)
        #pragma unroll
        for (int j = 0; j < 16; j++)
            #pragma unroll
            for (int q = 0; q < 4; q++) acc[i][j][q] = 0.f;

    for (int ch = 0; ch < NCH; ch++) {
        if (ch + 1 < NCH) prefetch(ch + 1);
        #pragma unroll
        for (int ks = 0; ks < 2; ks++) {
            int r = lane & 15;
            int kb = ks * 16 + ((lane >> 4) << 3);
            uint32_t a[2][4];
            #pragma unroll
            for (int mf = 0; mf < 2; mf++) {
                uint32_t off = (uint32_t)((wm * 32 + mf * 16 + r) * STRIDE_A + (ch * 32 + kb) * 2);
                LDSM4(a[mf][0], a[mf][1], a[mf][2], a[mf][3], sb + off);
            }
            #pragma unroll
            for (int nq = 0; nq < 8; nq++) {
                uint32_t off = (uint32_t)((wn * 128 + nq * 16 + r) * 80 + kb * 2);
                uint32_t t0, t1, t2, t3;
                LDSM4(t0, t1, t2, t3, sb + SH_OFF + off);
                uint32_t bh0[2] = {t0, t2}, bh1[2] = {t1, t3};
                LDSM4(t0, t1, t2, t3, sb + SL_OFF + off);
                uint32_t bl0[2] = {t0, t2}, bl1[2] = {t1, t3};
                #pragma unroll
                for (int mf = 0; mf < 2; mf++) {
                    MMA_F16(acc[mf][nq * 2], a[mf], bh0);
                    MMA_F16(acc[mf][nq * 2], a[mf], bl0);
                    MMA_F16(acc[mf][nq * 2 + 1], a[mf], bh1);
                    MMA_F16(acc[mf][nq * 2 + 1], a[mf], bl1);
                }
            }
        }
        __syncthreads();
        if (ch + 1 < NCH) {
            stage();
            __syncthreads();
        }
    }

    // ---- epilogue ----
    if constexpr (LAYER == 1) {
        #pragma unroll
        for (int mf = 0; mf < 2; mf++)
            #pragma unroll
            for (int nf = 0; nf < 16; nf++) {
                int rr = row0 + wm * 32 + mf * 16 + (lane >> 2);
                int cc = wn * 128 + nf * 8 + (lane & 3) * 2;
                float bv0 = bias[cc], bv1 = bias[cc + 1];
                float v00 = fmaxf(acc[mf][nf][0] + bv0, 0.f);
                float v01 = fmaxf(acc[mf][nf][1] + bv1, 0.f);
                float v10 = fmaxf(acc[mf][nf][2] + bv0, 0.f);
                float v11 = fmaxf(acc[mf][nf][3] + bv1, 0.f);
                if (rr < M)
                    *(__half2*)(g_h1h + (size_t)rr * 256 + cc) = __floats2half2_rn(v00, v01);
                if (rr + 8 < M)
                    *(__half2*)(g_h1h + (size_t)(rr + 8) * 256 + cc) = __floats2half2_rn(v10, v11);
            }
    } else {
        // fused mean-pool: warp-reduce each 16-row fragment group, then global atomics
        #pragma unroll
        for (int mf = 0; mf < 2; mf++) {
            int rowbase = row0 + wm * 32 + mf * 16;
            if (rowbase >= M) continue;
            int rr = rowbase + (lane >> 2);
            int rlast = min(rowbase + 15, M - 1);
            int g0 = batch[rowbase] & (NG - 1);
            bool uni = (batch[rlast] & (NG - 1)) == g0;
            int ga = (rr < M) ? (batch[rr] & (NG - 1)) : -1;
            int gb = (rr + 8 < M) ? (batch[rr + 8] & (NG - 1)) : -1;
            #pragma unroll
            for (int nf = 0; nf < 16; nf++) {
                int cc = wn * 128 + nf * 8 + (lane & 3) * 2;
                float bv0 = bias[cc], bv1 = bias[cc + 1];
                float va0 = (ga >= 0) ? fmaxf(acc[mf][nf][0] + bv0, 0.f) : 0.f;
                float va1 = (ga >= 0) ? fmaxf(acc[mf][nf][1] + bv1, 0.f) : 0.f;
                float vb0 = (gb >= 0) ? fmaxf(acc[mf][nf][2] + bv0, 0.f) : 0.f;
                float vb1 = (gb >= 0) ? fmaxf(acc[mf][nf][3] + bv1, 0.f) : 0.f;
                if (uni) {
                    float s0 = va0 + vb0;
                    float s1 = va1 + vb1;
                    #pragma unroll
                    for (int d = 16; d >= 4; d >>= 1) {
                        s0 += __shfl_down_sync(0xffffffffu, s0, d);
                        s1 += __shfl_down_sync(0xffffffffu, s1, d);
                    }
                    if (lane < 4) {
                        atomicAdd(&g_sums[g0 * 256 + cc], s0);
                        atomicAdd(&g_sums[g0 * 256 + cc + 1], s1);
                    }
                } else {
                    if (ga >= 0) {
                        atomicAdd(&g_sums[ga * 256 + cc], va0);
                        atomicAdd(&g_sums[ga * 256 + cc + 1], va1);
                    }
                    if (gb >= 0) {
                        atomicAdd(&g_sums[gb * 256 + cc], vb0);
                        atomicAdd(&g_sums[gb * 256 + cc + 1], vb1);
                    }
                }
            }
        }
    }
}

// ---------------- final ----------------
__global__ void final_kernel(const float* __restrict__ Wl,
                             const float* __restrict__ bl,
                             float* __restrict__ out) {
    int idx = threadIdx.x;
    int g = idx >> 1, c = idx & 1;
    float inv = 1.0f / fmaxf(g_cnt[g], 1.0f);
    float acc = bl[c];
    #pragma unroll 8
    for (int k = 0; k < 256; k++)
        acc = fmaf(g_sums[g * 256 + k] * inv, Wl[k * 2 + c], acc);
    out[idx] = acc;
}

// ---------------- launch ----------------
extern "C" void kernel_launch(void* const* d_in, const int* in_sizes, int n_in,
                              void* d_out, int out_size) {
    const float* x     = (const float*)d_in[0];
    const int*   ei    = (const int*)d_in[1];
    const int*   batch = (const int*)d_in[2];
    const float* W1    = (const float*)d_in[3];
    const float* b1    = (const float*)d_in[4];
    const float* W2    = (const float*)d_in[5];
    const float* b2    = (const float*)d_in[6];
    const float* Wl    = (const float*)d_in[7];
    const float* bl    = (const float*)d_in[8];
    float* out = (float*)d_out;

    int N = in_sizes[0] / 128;
    int E = in_sizes[1] / 2;
    int nb = (N + 1023) / 1024;

    // dynamic smem sizes: A tile (128*stride) + W hi/lo stage (2*20480)
    const int smem1 = 128 * (128 * 2 + 16) + 40960;   // 75776
    const int smem2 = 128 * (256 * 2 + 16) + 40960;   // 108544
    cudaFuncSetAttribute(fused_layer<1>, cudaFuncAttributeMaxDynamicSharedMemorySize, smem1);
    cudaFuncSetAttribute(fused_layer<2>, cudaFuncAttributeMaxDynamicSharedMemorySize, smem2);

    int prep_span = E;
    if (N * 32 > prep_span) prep_span = N * 32;
    if (256 * 128 + 256 * 256 > prep_span) prep_span = 256 * 128 + 256 * 256;

    // prep
    init_kernel<<<(N + 255) / 256, 256>>>(N);
    prep_all<<<(prep_span + 255) / 256, 256>>>(ei, batch, (const float4*)x, W1, W2, E, N);
    scan1<<<nb, 1024>>>(N);
    scan2<<<1, 128>>>(nb, N);
    scan3<<<(N + 255) / 256, 256>>>(N);
    fill_kernel<<<(E + 255) / 256, 256>>>(ei, E, N);

    int mtiles = (N + 127) / 128;
    // layer 1 (gather + GEMM fused)
    fused_layer<1><<<mtiles, 256, smem1>>>(b1, batch, N);
    // layer 2 (gather + GEMM + mean-pool fused)
    fused_layer<2><<<mtiles, 256, smem2>>>(b2, batch, N);
    // final
    final_kernel<<<1, 128>>>(Wl, bl, out);
}

// round 16
// speedup vs baseline: 2.1993x; 2.1993x over previous
#include <cuda_runtime.h>
#include <cuda_fp16.h>
#include <cstdint>

// ---------------- problem constants ----------------
#define MAXN 100000
#define MAXE 3200000
#define NG   64

__device__ __forceinline__ uint32_t smem_to_u32(const void* p) {
    uint32_t a;
    asm("{ .reg .u64 t; cvta.to.shared.u64 t, %1; cvt.u32.u64 %0, t; }" : "=r"(a) : "l"(p));
    return a;
}
#define LDSM4(r0, r1, r2, r3, addr) \
    asm volatile("ldmatrix.sync.aligned.m8n8.x4.shared.b16 {%0,%1,%2,%3}, [%4];" \
        : "=r"(r0), "=r"(r1), "=r"(r2), "=r"(r3) : "r"(addr))
#define MMA_F16(d, a, b) \
    asm volatile("mma.sync.aligned.m16n8k16.row.col.f32.f16.f16.f32 " \
        "{%0,%1,%2,%3}, {%4,%5,%6,%7}, {%8,%9}, {%0,%1,%2,%3};" \
        : "+f"((d)[0]), "+f"((d)[1]), "+f"((d)[2]), "+f"((d)[3]) \
        : "r"((a)[0]), "r"((a)[1]), "r"((a)[2]), "r"((a)[3]), "r"((b)[0]), "r"((b)[1]))

// ---------------- device scratch (referenced ONLY from device code) ----------------
__device__ int   g_deg[MAXN];
__device__ float g_dinv[MAXN];
__device__ int   g_colptr[MAXN + 1];
__device__ int   g_cursor[MAXN];
__device__ int   g_blocksum[128];
__device__ int   g_bloff[128];
__device__ int2  g_edge[MAXE];
__device__ __align__(16) __half g_xh[(size_t)MAXN * 128];    // x in fp16
__device__ __align__(16) __half g_h1h[(size_t)MAXN * 256];   // h1 in fp16
__device__ __align__(16) __half g_a1h[(size_t)MAXN * 128];   // agg1 fp16
__device__ __align__(16) __half g_a2h[(size_t)MAXN * 256];   // agg2 fp16
__device__ __align__(16) __half g_b1hi[256 * 128];
__device__ __align__(16) __half g_b1lo[256 * 128];
__device__ __align__(16) __half g_b2hi[256 * 256];
__device__ __align__(16) __half g_b2lo[256 * 256];
__device__ float g_sums[NG * 256];
__device__ float g_cnt[NG];

// ---------------- prep kernels ----------------
__global__ void init_kernel(int n) {
    int i = blockIdx.x * blockDim.x + threadIdx.x;
    if (i < n) g_deg[i] = 0;
    if (i < NG * 256) g_sums[i] = 0.f;
    if (i < NG) g_cnt[i] = 0.f;
}

// fused: degree atomics + graph counts + x->fp16 + weight transpose/split
__global__ void prep_all(const int* __restrict__ ei, const int* __restrict__ batch,
                         const float4* __restrict__ X,
                         const float* __restrict__ W1, const float* __restrict__ W2,
                         int E, int n) {
    int e = blockIdx.x * blockDim.x + threadIdx.x;
    if (e < E) {
        unsigned c = (unsigned)ei[E + e];
        if (c < (unsigned)n) atomicAdd(&g_deg[c], 1);
    }
    if (e < n) atomicAdd(&g_cnt[batch[e] & (NG - 1)], 1.0f);
    if (e < n * 32) {
        float4 v = X[e];
        union { __half2 h[2]; uint2 u; } o;
        o.h[0] = __floats2half2_rn(v.x, v.y);
        o.h[1] = __floats2half2_rn(v.z, v.w);
        *(uint2*)(g_xh + (size_t)e * 4) = o.u;
    }
    if (e < 256 * 128) {
        int k = e & 127, nn = e >> 7;
        float w = W1[k * 256 + nn];
        __half h = __float2half_rn(w);
        g_b1hi[e] = h;
        g_b1lo[e] = __float2half_rn(w - __half2float(h));
    } else if (e < 256 * 128 + 256 * 256) {
        int j = e - 256 * 128;
        int k = j & 255, nn = j >> 8;
        float w = W2[k * 256 + nn];
        __half h = __float2half_rn(w);
        g_b2hi[j] = h;
        g_b2lo[j] = __float2half_rn(w - __half2float(h));
    }
}

// 3-phase multiblock scan (scan1 also computes dinv)
__global__ void scan1(int n) {
    __shared__ int wsum[32];
    int i = blockIdx.x * 1024 + threadIdx.x;
    int lane = threadIdx.x & 31, wid = threadIdx.x >> 5;
    int v = (i < n) ? g_deg[i] : 0;
    if (i < n) g_dinv[i] = rsqrtf((float)(v + 1));   // +1 self loop
    int s = v;
    #pragma unroll
    for (int off = 1; off < 32; off <<= 1) {
        int t = __shfl_up_sync(0xffffffffu, s, off);
        if (lane >= off) s += t;
    }
    if (lane == 31) wsum[wid] = s;
    __syncthreads();
    if (wid == 0) {
        int t = wsum[lane];
        int ss = t;
        #pragma unroll
        for (int off = 1; off < 32; off <<= 1) {
            int u = __shfl_up_sync(0xffffffffu, ss, off);
            if (lane >= off) ss += u;
        }
        wsum[lane] = ss - t;
    }
    __syncthreads();
    if (i < n) g_colptr[i] = wsum[wid] + s - v;
    if (threadIdx.x == 1023) g_blocksum[blockIdx.x] = wsum[31] + s;
}

__global__ void scan2(int nb, int n) {
    __shared__ int ws[4];
    int lane = threadIdx.x & 31, wid = threadIdx.x >> 5;
    int v = (threadIdx.x < nb) ? g_blocksum[threadIdx.x] : 0;
    int s = v;
    #pragma unroll
    for (int off = 1; off < 32; off <<= 1) {
        int t = __shfl_up_sync(0xffffffffu, s, off);
        if (lane >= off) s += t;
    }
    if (lane == 31) ws[wid] = s;
    __syncthreads();
    int base = 0;
    for (int w = 0; w < wid; w++) base += ws[w];
    int excl = base + s - v;
    if (threadIdx.x < nb) g_bloff[threadIdx.x] = excl;
    if (threadIdx.x == nb - 1) g_colptr[n] = excl + v;
}

__global__ void scan3(int n) {
    int i = blockIdx.x * blockDim.x + threadIdx.x;
    if (i < n) {
        int v = g_colptr[i] + g_bloff[i >> 10];
        g_colptr[i] = v;
        g_cursor[i] = v;
    }
}

__global__ void fill_kernel(const int* __restrict__ ei, int E, int n) {
    int e = blockIdx.x * blockDim.x + threadIdx.x;
    if (e >= E) return;
    unsigned r = (unsigned)ei[e];
    unsigned c = (unsigned)ei[E + e];
    if (r >= (unsigned)n || c >= (unsigned)n) return;
    int p = atomicAdd(&g_cursor[c], 1);
    g_edge[p] = make_int2((int)r, __float_as_int(g_dinv[r] * g_dinv[c]));
}

// ---------------- aggregation (CSR gather of fp16 rows, fp32 accumulate) --------
__device__ __forceinline__ void fma_h4(float4& acc, uint2 u, float w) {
    union { __half2 h[2]; uint2 u2; } cv;
    cv.u2 = u;
    float2 f0 = __half22float2(cv.h[0]), f1 = __half22float2(cv.h[1]);
    acc.x = fmaf(f0.x, w, acc.x);
    acc.y = fmaf(f0.y, w, acc.y);
    acc.z = fmaf(f1.x, w, acc.z);
    acc.w = fmaf(f1.y, w, acc.w);
}
__device__ __forceinline__ void fma_h8(float* a, uint4 u, float w) {
    union { __half2 h[4]; uint4 u4; } cv;
    cv.u4 = u;
    float2 f0 = __half22float2(cv.h[0]), f1 = __half22float2(cv.h[1]);
    float2 f2 = __half22float2(cv.h[2]), f3 = __half22float2(cv.h[3]);
    a[0] = fmaf(f0.x, w, a[0]); a[1] = fmaf(f0.y, w, a[1]);
    a[2] = fmaf(f1.x, w, a[2]); a[3] = fmaf(f1.y, w, a[3]);
    a[4] = fmaf(f2.x, w, a[4]); a[5] = fmaf(f2.y, w, a[5]);
    a[6] = fmaf(f3.x, w, a[6]); a[7] = fmaf(f3.y, w, a[7]);
}

// layer 1, D=128: warp per node, lane owns 4 cols (uint2 = 8B)
__global__ void agg_d128(int n) {
    int node = blockIdx.x * 8 + (threadIdx.x >> 5);
    if (node >= n) return;
    int lane = threadIdx.x & 31;
    float di = g_dinv[node];
    float self = di * di;
    const uint2* Xh = (const uint2*)g_xh;
    union { __half2 h[2]; uint2 u; } cv;
    cv.u = Xh[(size_t)node * 32 + lane];
    float2 f0 = __half22float2(cv.h[0]), f1 = __half22float2(cv.h[1]);
    float4 acc = make_float4(f0.x * self, f0.y * self, f1.x * self, f1.y * self);
    int s = g_colptr[node], e = g_colptr[node + 1];
    int p = s;
    for (; p + 4 <= e; p += 4) {
        int2 e0 = g_edge[p], e1 = g_edge[p + 1], e2 = g_edge[p + 2], e3 = g_edge[p + 3];
        uint2 u0 = Xh[(size_t)e0.x * 32 + lane];
        uint2 u1 = Xh[(size_t)e1.x * 32 + lane];
        uint2 u2 = Xh[(size_t)e2.x * 32 + lane];
        uint2 u3 = Xh[(size_t)e3.x * 32 + lane];
        fma_h4(acc, u0, __int_as_float(e0.y));
        fma_h4(acc, u1, __int_as_float(e1.y));
        fma_h4(acc, u2, __int_as_float(e2.y));
        fma_h4(acc, u3, __int_as_float(e3.y));
    }
    for (; p < e; p++) {
        int2 ed = g_edge[p];
        fma_h4(acc, Xh[(size_t)ed.x * 32 + lane], __int_as_float(ed.y));
    }
    union { __half2 h[2]; uint2 u; } o;
    o.h[0] = __floats2half2_rn(acc.x, acc.y);
    o.h[1] = __floats2half2_rn(acc.z, acc.w);
    *(uint2*)(g_a1h + (size_t)node * 128 + lane * 4) = o.u;
}

// layer 2, D=256: warp per node, lane owns 8 cols (uint4 = 16B)
__global__ void agg_d256(int n) {
    int node = blockIdx.x * 8 + (threadIdx.x >> 5);
    if (node >= n) return;
    int lane = threadIdx.x & 31;
    const uint4* Xh = (const uint4*)g_h1h;
    float di = g_dinv[node];
    float self = di * di;
    union { __half2 h[4]; uint4 u; } cv;
    cv.u = Xh[(size_t)node * 32 + lane];
    float a[8];
    {
        float2 f0 = __half22float2(cv.h[0]), f1 = __half22float2(cv.h[1]);
        float2 f2 = __half22float2(cv.h[2]), f3 = __half22float2(cv.h[3]);
        a[0] = f0.x * self; a[1] = f0.y * self;
        a[2] = f1.x * self; a[3] = f1.y * self;
        a[4] = f2.x * self; a[5] = f2.y * self;
        a[6] = f3.x * self; a[7] = f3.y * self;
    }
    int s = g_colptr[node], e = g_colptr[node + 1];
    int p = s;
    for (; p + 4 <= e; p += 4) {
        int2 e0 = g_edge[p], e1 = g_edge[p + 1], e2 = g_edge[p + 2], e3 = g_edge[p + 3];
        uint4 u0 = Xh[(size_t)e0.x * 32 + lane];
        uint4 u1 = Xh[(size_t)e1.x * 32 + lane];
        uint4 u2 = Xh[(size_t)e2.x * 32 + lane];
        uint4 u3 = Xh[(size_t)e3.x * 32 + lane];
        fma_h8(a, u0, __int_as_float(e0.y));
        fma_h8(a, u1, __int_as_float(e1.y));
        fma_h8(a, u2, __int_as_float(e2.y));
        fma_h8(a, u3, __int_as_float(e3.y));
    }
    for (; p < e; p++) {
        int2 ed = g_edge[p];
        fma_h8(a, Xh[(size_t)ed.x * 32 + lane], __int_as_float(ed.y));
    }
    union { __half2 h[4]; uint4 u; } o;
    o.h[0] = __floats2half2_rn(a[0], a[1]);
    o.h[1] = __floats2half2_rn(a[2], a[3]);
    o.h[2] = __floats2half2_rn(a[4], a[5]);
    o.h[3] = __floats2half2_rn(a[6], a[7]);
    *(uint4*)(g_a2h + (size_t)node * 256 + lane * 8) = o.u;
}

// ---------------- HMMA fp16 (A single, W hi/lo) GEMM + bias + relu ----------------
// C[M,256] = A[M,K] @ W[K,256]. Block tile 128x128, 8 warps (4Mx2N), warp 32x64.
// Inner loop consumes B fragments immediately after ldmatrix (low live regs)
// so 2 CTAs/SM fit without spills.
// LAYER 1: writes h1 fp16. LAYER 2: fused mean-pool via warp-reduced global atomics.
template<int LAYER>
__global__ __launch_bounds__(256, 2) void gemm_mma(const float* __restrict__ bias,
                                                   const int* __restrict__ batch, int M) {
    constexpr int K = (LAYER == 1) ? 128 : 256;
    constexpr int NCH = K / 32;
    const __half* A  = (LAYER == 1) ? g_a1h : g_a2h;
    const __half* WH = (LAYER == 1) ? g_b1hi : g_b2hi;
    const __half* WL = (LAYER == 1) ? g_b1lo : g_b2lo;

    __shared__ __align__(16) char smem[30720];
    uint32_t sb = smem_to_u32(smem);
    const uint32_t SA = 0, SH = 10240, SL = 20480;

    int tid = threadIdx.x, lane = tid & 31, wid = tid >> 5;
    int row0 = blockIdx.x * 128, col0 = blockIdx.y * 128;
    int wm = wid & 3, wn = wid >> 2;

    float acc[2][8][4];
    #pragma unroll
    for (int i = 0; i < 2; i++)
        #pragma unroll
        for (int j = 0; j < 8; j++)
            #pragma unroll
            for (int q = 0; q < 4; q++) acc[i][j][q] = 0.f;

    uint4 pA[2], pH[2], pL[2];
    auto prefetch = [&](int ch) {
        #pragma unroll
        for (int g = 0; g < 2; g++) {
            int idx = tid + g * 256;
            int r = idx >> 2, c = idx & 3;
            int gk = ch * 32 + c * 8;
            int ar = row0 + r;
            pA[g] = (ar < M) ? *(const uint4*)(A + (size_t)ar * K + gk)
                             : make_uint4(0, 0, 0, 0);
            int br = col0 + r;
            pH[g] = *(const uint4*)(WH + (size_t)br * K + gk);
            pL[g] = *(const uint4*)(WL + (size_t)br * K + gk);
        }
    };
    auto stage = [&]() {
        #pragma unroll
        for (int g = 0; g < 2; g++) {
            int idx = tid + g * 256;
            int r = idx >> 2, c = idx & 3;
            uint32_t o = (uint32_t)(r * 80 + c * 16);
            *(uint4*)(smem + SA + o) = pA[g];
            *(uint4*)(smem + SH + o) = pH[g];
            *(uint4*)(smem + SL + o) = pL[g];
        }
    };

    prefetch(0);
    stage();
    __syncthreads();

    for (int ch = 0; ch < NCH; ch++) {
        if (ch + 1 < NCH) prefetch(ch + 1);
        #pragma unroll
        for (int ks = 0; ks < 2; ks++) {
            int r = lane & 15;
            int kb = ks * 16 + ((lane >> 4) << 3);
            uint32_t a[2][4];
            #pragma unroll
            for (int mf = 0; mf < 2; mf++) {
                uint32_t off = (uint32_t)((wm * 32 + mf * 16 + r) * 80 + kb * 2);
                LDSM4(a[mf][0], a[mf][1], a[mf][2], a[mf][3], sb + SA + off);
            }
            #pragma unroll
            for (int nq = 0; nq < 4; nq++) {
                uint32_t off = (uint32_t)((wn * 64 + nq * 16 + r) * 80 + kb * 2);
                uint32_t t0, t1, t2, t3;
                LDSM4(t0, t1, t2, t3, sb + SH + off);
                {
                    uint32_t b0[2] = {t0, t2}, b1[2] = {t1, t3};
                    #pragma unroll
                    for (int mf = 0; mf < 2; mf++) {
                        MMA_F16(acc[mf][nq * 2], a[mf], b0);
                        MMA_F16(acc[mf][nq * 2 + 1], a[mf], b1);
                    }
                }
                LDSM4(t0, t1, t2, t3, sb + SL + off);
                {
                    uint32_t b0[2] = {t0, t2}, b1[2] = {t1, t3};
                    #pragma unroll
                    for (int mf = 0; mf < 2; mf++) {
                        MMA_F16(acc[mf][nq * 2], a[mf], b0);
                        MMA_F16(acc[mf][nq * 2 + 1], a[mf], b1);
                    }
                }
            }
        }
        __syncthreads();
        if (ch + 1 < NCH) {
            stage();
            __syncthreads();
        }
    }

    if constexpr (LAYER == 1) {
        // write h1 fp16
        #pragma unroll
        for (int mf = 0; mf < 2; mf++)
            #pragma unroll
            for (int nf = 0; nf < 8; nf++) {
                int rr = row0 + wm * 32 + mf * 16 + (lane >> 2);
                int cc = col0 + wn * 64 + nf * 8 + (lane & 3) * 2;
                float bv0 = bias[cc], bv1 = bias[cc + 1];
                float v00 = fmaxf(acc[mf][nf][0] + bv0, 0.f);
                float v01 = fmaxf(acc[mf][nf][1] + bv1, 0.f);
                float v10 = fmaxf(acc[mf][nf][2] + bv0, 0.f);
                float v11 = fmaxf(acc[mf][nf][3] + bv1, 0.f);
                if (rr < M)
                    *(__half2*)(g_h1h + (size_t)rr * 256 + cc) = __floats2half2_rn(v00, v01);
                if (rr + 8 < M)
                    *(__half2*)(g_h1h + (size_t)(rr + 8) * 256 + cc) = __floats2half2_rn(v10, v11);
            }
    } else {
        // fused mean-pool: warp-reduce each 16-row fragment group, then global atomics
        #pragma unroll
        for (int mf = 0; mf < 2; mf++) {
            int rowbase = row0 + wm * 32 + mf * 16;
            if (rowbase >= M) continue;
            int rr = rowbase + (lane >> 2);
            int rlast = min(rowbase + 15, M - 1);
            int g0 = batch[rowbase] & (NG - 1);
            bool uni = (batch[rlast] & (NG - 1)) == g0;
            int ga = (rr < M) ? (batch[rr] & (NG - 1)) : -1;
            int gb = (rr + 8 < M) ? (batch[rr + 8] & (NG - 1)) : -1;
            #pragma unroll
            for (int nf = 0; nf < 8; nf++) {
                int cc = col0 + wn * 64 + nf * 8 + (lane & 3) * 2;
                float bv0 = bias[cc], bv1 = bias[cc + 1];
                float va0 = (ga >= 0) ? fmaxf(acc[mf][nf][0] + bv0, 0.f) : 0.f;
                float va1 = (ga >= 0) ? fmaxf(acc[mf][nf][1] + bv1, 0.f) : 0.f;
                float vb0 = (gb >= 0) ? fmaxf(acc[mf][nf][2] + bv0, 0.f) : 0.f;
                float vb1 = (gb >= 0) ? fmaxf(acc[mf][nf][3] + bv1, 0.f) : 0.f;
                if (uni) {
                    float s0 = va0 + vb0;
                    float s1 = va1 + vb1;
                    #pragma unroll
                    for (int d = 16; d >= 4; d >>= 1) {
                        s0 += __shfl_down_sync(0xffffffffu, s0, d);
                        s1 += __shfl_down_sync(0xffffffffu, s1, d);
                    }
                    if (lane < 4) {
                        atomicAdd(&g_sums[g0 * 256 + cc], s0);
                        atomicAdd(&g_sums[g0 * 256 + cc + 1], s1);
                    }
                } else {
                    if (ga >= 0) {
                        atomicAdd(&g_sums[ga * 256 + cc], va0);
                        atomicAdd(&g_sums[ga * 256 + cc + 1], va1);
                    }
                    if (gb >= 0) {
                        atomicAdd(&g_sums[gb * 256 + cc], vb0);
                        atomicAdd(&g_sums[gb * 256 + cc + 1], vb1);
                    }
                }
            }
        }
    }
}

// ---------------- final ----------------
__global__ void final_kernel(const float* __restrict__ Wl,
                             const float* __restrict__ bl,
                             float* __restrict__ out) {
    int idx = threadIdx.x;
    int g = idx >> 1, c = idx & 1;
    float inv = 1.0f / fmaxf(g_cnt[g], 1.0f);
    float acc = bl[c];
    #pragma unroll 8
    for (int k = 0; k < 256; k++)
        acc = fmaf(g_sums[g * 256 + k] * inv, Wl[k * 2 + c], acc);
    out[idx] = acc;
}

// ---------------- launch ----------------
extern "C" void kernel_launch(void* const* d_in, const int* in_sizes, int n_in,
                              void* d_out, int out_size) {
    const float* x     = (const float*)d_in[0];
    const int*   ei    = (const int*)d_in[1];
    const int*   batch = (const int*)d_in[2];
    const float* W1    = (const float*)d_in[3];
    const float* b1    = (const float*)d_in[4];
    const float* W2    = (const float*)d_in[5];
    const float* b2    = (const float*)d_in[6];
    const float* Wl    = (const float*)d_in[7];
    const float* bl    = (const float*)d_in[8];
    float* out = (float*)d_out;

    int N = in_sizes[0] / 128;
    int E = in_sizes[1] / 2;
    int nb = (N + 1023) / 1024;

    int prep_span = E;
    if (N * 32 > prep_span) prep_span = N * 32;
    if (256 * 128 + 256 * 256 > prep_span) prep_span = 256 * 128 + 256 * 256;

    // prep
    init_kernel<<<(N + 255) / 256, 256>>>(N);
    prep_all<<<(prep_span + 255) / 256, 256>>>(ei, batch, (const float4*)x, W1, W2, E, N);
    scan1<<<nb, 1024>>>(N);
    scan2<<<1, 128>>>(nb, N);
    scan3<<<(N + 255) / 256, 256>>>(N);
    fill_kernel<<<(E + 255) / 256, 256>>>(ei, E, N);

    int mtiles = (N + 127) / 128;
    dim3 ggrid(mtiles, 2);
    // layer 1
    agg_d128<<<(N + 7) / 8, 256>>>(N);
    gemm_mma<1><<<ggrid, 256>>>(b1, batch, N);
    // layer 2 (mean-pool fused into epilogue)
    agg_d256<<<(N + 7) / 8, 256>>>(N);
    gemm_mma<2><<<ggrid, 256>>>(b2, batch, N);
    // final
    final_kernel<<<1, 128>>>(Wl, bl, out);
}